// round 14
// baseline (speedup 1.0000x reference)
#include <cuda_runtime.h>
#include <cuda_bf16.h>
#include <cstdint>

#define B_N   256
#define C_D   512
#define HW    784
#define HW4   196
#define M_N   65536
#define TOPK  32

// ---------------- scratch (device globals; no allocation allowed) ----------------
__device__ float g_q[B_N * C_D];                       // pooled query (fp32)
__device__ __nv_bfloat16 g_qh[B_N * C_D];              // normalized query, bf16 hi
__device__ __nv_bfloat16 g_ql[B_N * C_D];              // normalized query, bf16 lo
__device__ __nv_bfloat16 g_kh[(size_t)M_N * C_D];      // normalized keys, bf16 hi (64 MB)
__device__ __nv_bfloat16 g_kl[(size_t)M_N * C_D];      // normalized keys, bf16 lo (64 MB)
__device__ float g_sim[(size_t)B_N * M_N];             // 64 MB similarity matrix
__device__ float g_tv[B_N * TOPK];
__device__ int   g_ti[B_N * TOPK];
__device__ float g_match[B_N * C_D];

// ---------------- small helpers ----------------
__device__ __forceinline__ unsigned int fkey(float f) {
    unsigned int u = __float_as_uint(f);
    return (u & 0x80000000u) ? ~u : (u | 0x80000000u);
}
__device__ __forceinline__ float unfkey(unsigned int u) {
    u = (u & 0x80000000u) ? (u & 0x7fffffffu) : ~u;
    return __uint_as_float(u);
}
__device__ __forceinline__ uint32_t smem_u32(const void* p) {
    uint32_t a;
    asm("{ .reg .u64 t; cvta.to.shared.u64 t, %1; cvt.u32.u64 %0, t; }" : "=r"(a) : "l"(p));
    return a;
}
__device__ __forceinline__ void cp16(uint32_t dst, const void* src) {
    asm volatile("cp.async.cg.shared.global [%0], [%1], 16;" :: "r"(dst), "l"(src));
}
template <int N>
__device__ __forceinline__ void cp_wait() {
    asm volatile("cp.async.wait_group %0;" :: "n"(N) : "memory");
}
__device__ __forceinline__ void ldsm4(uint32_t* r, uint32_t addr) {
    asm volatile("ldmatrix.sync.aligned.m8n8.x4.shared.b16 {%0,%1,%2,%3}, [%4];"
        : "=r"(r[0]), "=r"(r[1]), "=r"(r[2]), "=r"(r[3]) : "r"(addr));
}
__device__ __forceinline__ void mma_bf16(float* d, const uint32_t* a, const uint32_t* b) {
    asm volatile("mma.sync.aligned.m16n8k16.row.col.f32.bf16.bf16.f32 "
        "{%0,%1,%2,%3}, {%4,%5,%6,%7}, {%8,%9}, {%0,%1,%2,%3};"
        : "+f"(d[0]), "+f"(d[1]), "+f"(d[2]), "+f"(d[3])
        : "r"(a[0]), "r"(a[1]), "r"(a[2]), "r"(a[3]), "r"(b[0]), "r"(b[1]));
}
__device__ __forceinline__ uint32_t swz(uint32_t base, int row, int slot) {
    return base + (uint32_t)(row * 128) + (uint32_t)(((slot ^ (row & 7)) & 7) << 4);
}

// ---------------- 1. global average pool ----------------
__global__ void pool_kernel(const float* __restrict__ x) {
    int wid  = (blockIdx.x * blockDim.x + threadIdx.x) >> 5;
    int lane = threadIdx.x & 31;
    const float4* p = reinterpret_cast<const float4*>(x) + (size_t)wid * HW4;
    float s = 0.f;
    #pragma unroll
    for (int i = 0; i < 7; ++i) {
        int j = lane + i * 32;
        if (j < HW4) { float4 v = p[j]; s += (v.x + v.y) + (v.z + v.w); }
    }
    #pragma unroll
    for (int o = 16; o; o >>= 1) s += __shfl_xor_sync(0xffffffffu, s, o);
    if (lane == 0) g_q[wid] = s * (1.0f / (float)HW);
}

// ---------------- 2. normalize query + split to bf16 hi/lo ----------------
__global__ void qnorm_kernel() {
    int b = blockIdx.x;
    int t = threadIdx.x;            // 128 threads, one float4 each
    float4 v = reinterpret_cast<const float4*>(g_q + (size_t)b * C_D)[t];
    float ss = v.x*v.x + v.y*v.y + v.z*v.z + v.w*v.w;
    #pragma unroll
    for (int o = 16; o; o >>= 1) ss += __shfl_xor_sync(0xffffffffu, ss, o);
    __shared__ float sred[4];
    if ((t & 31) == 0) sred[t >> 5] = ss;
    __syncthreads();
    float inv = 1.0f / sqrtf(sred[0] + sred[1] + sred[2] + sred[3]);
    float n[4] = { v.x*inv, v.y*inv, v.z*inv, v.w*inv };
    __nv_bfloat16 h[4]; float l[4];
    #pragma unroll
    for (int i = 0; i < 4; ++i) { h[i] = __float2bfloat16_rn(n[i]); l[i] = n[i] - __bfloat162float(h[i]); }
    __nv_bfloat162* qh2 = reinterpret_cast<__nv_bfloat162*>(g_qh + (size_t)b * C_D);
    __nv_bfloat162* ql2 = reinterpret_cast<__nv_bfloat162*>(g_ql + (size_t)b * C_D);
    qh2[2*t]   = __nv_bfloat162(h[0], h[1]);
    qh2[2*t+1] = __nv_bfloat162(h[2], h[3]);
    ql2[2*t]   = __floats2bfloat162_rn(l[0], l[1]);
    ql2[2*t+1] = __floats2bfloat162_rn(l[2], l[3]);
}

// ---------------- 3. normalize keys + split to bf16 hi/lo (warp per row) ----------------
__global__ void kprep_kernel(const float* __restrict__ keys) {
    int row  = (blockIdx.x * blockDim.x + threadIdx.x) >> 5;
    int lane = threadIdx.x & 31;
    const float4* p = reinterpret_cast<const float4*>(keys + (size_t)row * C_D);
    float4 v[4];
    float ss = 0.f;
    #pragma unroll
    for (int i = 0; i < 4; ++i) {
        v[i] = p[lane + 32 * i];
        ss += v[i].x*v[i].x + v[i].y*v[i].y + v[i].z*v[i].z + v[i].w*v[i].w;
    }
    #pragma unroll
    for (int o = 16; o; o >>= 1) ss += __shfl_xor_sync(0xffffffffu, ss, o);
    float inv = 1.0f / sqrtf(ss);
    __nv_bfloat162* kh2 = reinterpret_cast<__nv_bfloat162*>(g_kh + (size_t)row * C_D);
    __nv_bfloat162* kl2 = reinterpret_cast<__nv_bfloat162*>(g_kl + (size_t)row * C_D);
    #pragma unroll
    for (int i = 0; i < 4; ++i) {
        int u = lane + 32 * i;                  // float4 unit -> cols [4u, 4u+4)
        float n[4] = { v[i].x*inv, v[i].y*inv, v[i].z*inv, v[i].w*inv };
        __nv_bfloat16 h[4]; float l[4];
        #pragma unroll
        for (int j = 0; j < 4; ++j) { h[j] = __float2bfloat16_rn(n[j]); l[j] = n[j] - __bfloat162float(h[j]); }
        kh2[2*u]   = __nv_bfloat162(h[0], h[1]);
        kh2[2*u+1] = __nv_bfloat162(h[2], h[3]);
        kl2[2*u]   = __floats2bfloat162_rn(l[0], l[1]);
        kl2[2*u+1] = __floats2bfloat162_rn(l[2], l[3]);
    }
}

// ---------------- 4. sim GEMM via HMMA mma.sync bf16 (3-term hi/lo split) ----------------
// CTA tile 128(b) x 128(m). 8 warps as 4(m-rows) x 2(n-cols): warp tile 32x64.
// K chunks of 64 cols; smem 128B rows with SW128 xor swizzle; 3-stage cp.async.
// Grid is (2 batch-slabs, 512 m-tiles): the two CTAs sharing a key tile are
// ADJACENT in linear block order -> second kh/kl read hits L2 instead of DRAM.
#define GEMM_BM 128
#define GEMM_BN 128
#define KC      64
#define NCH     (C_D / KC)       // 8
#define MAT_SZ  16384u           // 128 rows x 128 B
#define STG_SZ  65536u           // qh | ql | kh | kl

extern __shared__ char g_dynsmem[];

__device__ __forceinline__ void load_stage(int ch, int tid, int mm, int bb, uint32_t stg) {
    const int koff = ch * KC;
    const __nv_bfloat16* src0 = g_qh + (size_t)bb * C_D + koff;
    const __nv_bfloat16* src1 = g_ql + (size_t)bb * C_D + koff;
    const __nv_bfloat16* src2 = g_kh + (size_t)mm * C_D + koff;
    const __nv_bfloat16* src3 = g_kl + (size_t)mm * C_D + koff;
    const __nv_bfloat16* srcs[4] = { src0, src1, src2, src3 };
    #pragma unroll
    for (int m = 0; m < 4; ++m) {
        const uint32_t mb = stg + (uint32_t)m * MAT_SZ;
        const __nv_bfloat16* s = srcs[m];
        #pragma unroll
        for (int i = 0; i < 4; ++i) {
            int u = i * 256 + tid;            // 1024 x 16B transfers
            int r = u >> 3, sl = u & 7;
            cp16(mb + (uint32_t)(r * 128) + (uint32_t)(((sl ^ (r & 7)) & 7) << 4),
                 s + (size_t)r * C_D + sl * 8);
        }
    }
    asm volatile("cp.async.commit_group;" ::: "memory");
}

__global__ void __launch_bounds__(256, 1) gemm_hmma_kernel() {
    const int tid  = threadIdx.x;
    const int wid  = tid >> 5;
    const int lane = tid & 31;
    const int mm   = blockIdx.y * GEMM_BN;   // key tile (slow axis)
    const int bb   = blockIdx.x * GEMM_BM;   // batch slab (fast axis -> adjacent CTAs share keys)
    const int wrow = (wid & 3) * 32;      // warp m-offset within tile
    const int wcol = (wid >> 2) * 64;     // warp n-offset within tile
    const uint32_t sbase = (smem_u32(g_dynsmem) + 1023u) & ~1023u;

    float acc[2][8][4];
    #pragma unroll
    for (int i = 0; i < 2; ++i)
        #pragma unroll
        for (int j = 0; j < 8; ++j)
            #pragma unroll
            for (int q = 0; q < 4; ++q) acc[i][j][q] = 0.f;

    load_stage(0, tid, mm, bb, sbase + 0u * STG_SZ);
    load_stage(1, tid, mm, bb, sbase + 1u * STG_SZ);

    const int arow = ((lane >> 3) & 1) * 8 + (lane & 7);   // A ldmatrix row-in-tile
    const int brow = (lane >> 4) * 8 + (lane & 7);         // B ldmatrix row-in-pair

    for (int ch = 0; ch < NCH; ++ch) {
        if (ch < NCH - 1) cp_wait<1>(); else cp_wait<0>();
        __syncthreads();
        if (ch + 2 < NCH) load_stage(ch + 2, tid, mm, bb, sbase + (uint32_t)((ch + 2) % 3) * STG_SZ);

        const uint32_t st   = sbase + (uint32_t)(ch % 3) * STG_SZ;
        const uint32_t s_qh = st;
        const uint32_t s_ql = st + MAT_SZ;
        const uint32_t s_kh = st + 2u * MAT_SZ;
        const uint32_t s_kl = st + 3u * MAT_SZ;

        #pragma unroll
        for (int stp = 0; stp < 4; ++stp) {               // 4 x k16 per chunk
            uint32_t ah[2][4], al[2][4], bh[8][2], bl[8][2];
            const int aslot = 2 * stp + (lane >> 4);
            const int bslot = 2 * stp + ((lane >> 3) & 1);
            #pragma unroll
            for (int i = 0; i < 2; ++i) {
                int r = wrow + i * 16 + arow;
                ldsm4(ah[i], swz(s_qh, r, aslot));
                ldsm4(al[i], swz(s_ql, r, aslot));
            }
            #pragma unroll
            for (int jp = 0; jp < 4; ++jp) {
                int r = wcol + jp * 16 + brow;
                ldsm4(&bh[2 * jp][0], swz(s_kh, r, bslot));
                ldsm4(&bl[2 * jp][0], swz(s_kl, r, bslot));
            }
            #pragma unroll
            for (int i = 0; i < 2; ++i)
                #pragma unroll
                for (int j = 0; j < 8; ++j) {
                    mma_bf16(acc[i][j], ah[i], bh[j]);   // qh . kh
                    mma_bf16(acc[i][j], al[i], bh[j]);   // ql . kh
                    mma_bf16(acc[i][j], ah[i], bl[j]);   // qh . kl
                }
        }
    }

    // epilogue: direct global stores (rows = batch, cols = keys)
    #pragma unroll
    for (int i = 0; i < 2; ++i) {
        const int r0 = bb + wrow + i * 16 + (lane >> 2);
        #pragma unroll
        for (int j = 0; j < 8; ++j) {
            const int c = mm + wcol + j * 8 + 2 * (lane & 3);
            float* p = g_sim + (size_t)r0 * M_N + c;
            *reinterpret_cast<float2*>(p)                    = make_float2(acc[i][j][0], acc[i][j][1]);
            *reinterpret_cast<float2*>(p + (size_t)8 * M_N)  = make_float2(acc[i][j][2], acc[i][j][3]);
        }
    }
}

// ---------------- 5. per-row top-32 via 13-bit radix select ----------------
__global__ void __launch_bounds__(256) topk_kernel() {
    const int b   = blockIdx.x;
    const int tid = threadIdx.x;
    const float4* row4 = reinterpret_cast<const float4*>(g_sim + (size_t)b * M_N);

    __shared__ unsigned int       s_hist[8192];   // 32 KB; reused as eq-candidate list
    __shared__ unsigned int       s_coarse[256];
    __shared__ unsigned long long s_gt[TOPK];
    __shared__ unsigned long long s_rv[256];
    __shared__ int                s_rp[256];
    __shared__ int s_T, s_cntgt, s_nGT, s_nEQ;

    #pragma unroll
    for (int i = 0; i < 32; ++i) s_hist[tid + i * 256] = 0;
    if (tid == 0) { s_nGT = 0; s_nEQ = 0; }
    __syncthreads();

    for (int i = tid; i < M_N / 4; i += 256) {
        float4 v = row4[i];
        atomicAdd(&s_hist[fkey(v.x) >> 19], 1u);
        atomicAdd(&s_hist[fkey(v.y) >> 19], 1u);
        atomicAdd(&s_hist[fkey(v.z) >> 19], 1u);
        atomicAdd(&s_hist[fkey(v.w) >> 19], 1u);
    }
    __syncthreads();

    {
        unsigned int s = 0;
        #pragma unroll
        for (int j = 0; j < 32; ++j) s += s_hist[tid * 32 + j];
        s_coarse[tid] = s;
    }
    __syncthreads();
    if (tid == 0) {
        unsigned int acc = 0;
        int cb = 0;
        for (int t = 255; t >= 0; --t) {
            if (acc + s_coarse[t] >= TOPK) { cb = t; break; }
            acc += s_coarse[t];
        }
        int T = cb * 32;
        for (int j = 31; j >= 0; --j) {
            unsigned int c = s_hist[cb * 32 + j];
            if (acc + c >= TOPK) { T = cb * 32 + j; break; }
            acc += c;
        }
        s_T = T; s_cntgt = (int)acc;
    }
    __syncthreads();
    const int T      = s_T;
    const int cnt_gt = s_cntgt;
    __syncthreads();

    unsigned long long* s_eq = reinterpret_cast<unsigned long long*>(s_hist);

    for (int i = tid; i < M_N / 4; i += 256) {
        float4 v = row4[i];
        float vv[4] = { v.x, v.y, v.z, v.w };
        #pragma unroll
        for (int c = 0; c < 4; ++c) {
            unsigned int key = fkey(vv[c]);
            int bin = (int)(key >> 19);
            if (bin > T) {
                int p = atomicAdd(&s_nGT, 1);
                s_gt[p] = ((unsigned long long)key << 32) | (unsigned int)(4 * i + c);
            } else if (bin == T) {
                int p = atomicAdd(&s_nEQ, 1);
                if (p < 4096) s_eq[p] = ((unsigned long long)key << 32) | (unsigned int)(4 * i + c);
            }
        }
    }
    __syncthreads();
    const int nEQ  = min(s_nEQ, 4096);
    const int need = TOPK - cnt_gt;

    for (int i = tid; i < cnt_gt; i += 256) {
        unsigned long long e = s_gt[i];
        g_ti[b * TOPK + i] = (int)(unsigned int)e;
        g_tv[b * TOPK + i] = unfkey((unsigned int)(e >> 32));
    }

    for (int r = 0; r < need; ++r) {
        unsigned long long best = 0; int bp = -1;
        for (int i = tid; i < nEQ; i += 256) {
            unsigned long long v = s_eq[i];
            if (v > best) { best = v; bp = i; }
        }
        s_rv[tid] = best; s_rp[tid] = bp;
        __syncthreads();
        for (int sft = 128; sft > 0; sft >>= 1) {
            if (tid < sft && s_rv[tid + sft] > s_rv[tid]) {
                s_rv[tid] = s_rv[tid + sft]; s_rp[tid] = s_rp[tid + sft];
            }
            __syncthreads();
        }
        if (tid == 0) {
            unsigned long long e = s_rv[0];
            g_ti[b * TOPK + cnt_gt + r] = (int)(unsigned int)e;
            g_tv[b * TOPK + cnt_gt + r] = unfkey((unsigned int)(e >> 32));
            s_eq[s_rp[0]] = 0ull;
        }
        __syncthreads();
    }
}

// ---------------- 6. softmax + weighted gather of values ----------------
__global__ void matched_kernel(const float* __restrict__ values) {
    const int b = blockIdx.x;
    const int c = threadIdx.x;          // 512 threads
    __shared__ float sw[TOPK];
    __shared__ int   sidx[TOPK];
    if (c < TOPK) {
        sidx[c] = g_ti[b * TOPK + c];
        float v = g_tv[b * TOPK + c];
        float mx = v;
        #pragma unroll
        for (int o = 16; o; o >>= 1) mx = fmaxf(mx, __shfl_xor_sync(0xffffffffu, mx, o));
        float e = expf(v - mx);
        float s = e;
        #pragma unroll
        for (int o = 16; o; o >>= 1) s += __shfl_xor_sync(0xffffffffu, s, o);
        sw[c] = e / s;
    }
    __syncthreads();
    float acc = 0.f;
    #pragma unroll
    for (int k = 0; k < TOPK; ++k)
        acc += sw[k] * values[(size_t)sidx[k] * C_D + c];
    g_match[b * C_D + c] = acc;
}

// ---------------- 7. broadcast matched[b,c] over 28x28 spatial ----------------
__global__ void bcast_kernel(float* __restrict__ out) {
    int wid  = (blockIdx.x * blockDim.x + threadIdx.x) >> 5;
    int lane = threadIdx.x & 31;
    float v = g_match[wid];
    float4 vv = make_float4(v, v, v, v);
    float4* o = reinterpret_cast<float4*>(out) + (size_t)wid * HW4;
    #pragma unroll
    for (int i = 0; i < 7; ++i) {
        int j = lane + i * 32;
        if (j < HW4) o[j] = vv;
    }
}

// ---------------- launch ----------------
extern "C" void kernel_launch(void* const* d_in, const int* in_sizes, int n_in,
                              void* d_out, int out_size) {
    const float* x      = (const float*)d_in[0];
    const float* keys   = (const float*)d_in[1];
    const float* values = (const float*)d_in[2];
    float* out = (float*)d_out;

    static bool attr_done = false;
    const int gemm_smem = 3 * (int)STG_SZ + 1024;   // 3 stages + align slack
    if (!attr_done) {
        cudaFuncSetAttribute(gemm_hmma_kernel,
                             cudaFuncAttributeMaxDynamicSharedMemorySize, gemm_smem);
        attr_done = true;
    }

    pool_kernel <<< (B_N * C_D) / 8, 256 >>>(x);
    qnorm_kernel<<< B_N, 128 >>>();
    kprep_kernel<<< M_N / 8, 256 >>>(keys);
    gemm_hmma_kernel<<< dim3(B_N / GEMM_BM, M_N / GEMM_BN), 256, gemm_smem >>>();
    topk_kernel <<< B_N, 256 >>>();
    matched_kernel<<< B_N, C_D >>>(values);
    bcast_kernel<<< (B_N * C_D) / 8, 256 >>>(out);
}

// round 15
// speedup vs baseline: 1.0011x; 1.0011x over previous
#include <cuda_runtime.h>
#include <cuda_bf16.h>
#include <cstdint>

#define B_N   256
#define C_D   512
#define HW    784
#define HW4   196
#define M_N   65536
#define TOPK  32

// ---------------- scratch (device globals; no allocation allowed) ----------------
__device__ float g_q[B_N * C_D];                       // pooled query (fp32)
__device__ __nv_bfloat16 g_qh[B_N * C_D];              // normalized query, bf16 hi
__device__ __nv_bfloat16 g_ql[B_N * C_D];              // normalized query, bf16 lo
__device__ __nv_bfloat16 g_kh[(size_t)M_N * C_D];      // normalized keys, bf16 hi (64 MB)
__device__ __nv_bfloat16 g_kl[(size_t)M_N * C_D];      // normalized keys, bf16 lo (64 MB)
__device__ float g_sim[(size_t)B_N * M_N];             // 64 MB similarity matrix
__device__ float g_tv[B_N * TOPK];
__device__ int   g_ti[B_N * TOPK];
__device__ float g_match[B_N * C_D];

// ---------------- small helpers ----------------
__device__ __forceinline__ unsigned int fkey(float f) {
    unsigned int u = __float_as_uint(f);
    return (u & 0x80000000u) ? ~u : (u | 0x80000000u);
}
__device__ __forceinline__ float unfkey(unsigned int u) {
    u = (u & 0x80000000u) ? (u & 0x7fffffffu) : ~u;
    return __uint_as_float(u);
}
__device__ __forceinline__ uint32_t smem_u32(const void* p) {
    uint32_t a;
    asm("{ .reg .u64 t; cvta.to.shared.u64 t, %1; cvt.u32.u64 %0, t; }" : "=r"(a) : "l"(p));
    return a;
}
__device__ __forceinline__ void cp16(uint32_t dst, const void* src) {
    asm volatile("cp.async.cg.shared.global [%0], [%1], 16;" :: "r"(dst), "l"(src));
}
template <int N>
__device__ __forceinline__ void cp_wait() {
    asm volatile("cp.async.wait_group %0;" :: "n"(N) : "memory");
}
__device__ __forceinline__ void ldsm4(uint32_t* r, uint32_t addr) {
    asm volatile("ldmatrix.sync.aligned.m8n8.x4.shared.b16 {%0,%1,%2,%3}, [%4];"
        : "=r"(r[0]), "=r"(r[1]), "=r"(r[2]), "=r"(r[3]) : "r"(addr));
}
__device__ __forceinline__ void mma_bf16(float* d, const uint32_t* a, const uint32_t* b) {
    asm volatile("mma.sync.aligned.m16n8k16.row.col.f32.bf16.bf16.f32 "
        "{%0,%1,%2,%3}, {%4,%5,%6,%7}, {%8,%9}, {%0,%1,%2,%3};"
        : "+f"(d[0]), "+f"(d[1]), "+f"(d[2]), "+f"(d[3])
        : "r"(a[0]), "r"(a[1]), "r"(a[2]), "r"(a[3]), "r"(b[0]), "r"(b[1]));
}
__device__ __forceinline__ uint32_t swz(uint32_t base, int row, int slot) {
    return base + (uint32_t)(row * 128) + (uint32_t)(((slot ^ (row & 7)) & 7) << 4);
}

// ---------------- 1. global average pool ----------------
__global__ void pool_kernel(const float* __restrict__ x) {
    int wid  = (blockIdx.x * blockDim.x + threadIdx.x) >> 5;
    int lane = threadIdx.x & 31;
    const float4* p = reinterpret_cast<const float4*>(x) + (size_t)wid * HW4;
    float s = 0.f;
    #pragma unroll
    for (int i = 0; i < 7; ++i) {
        int j = lane + i * 32;
        if (j < HW4) { float4 v = p[j]; s += (v.x + v.y) + (v.z + v.w); }
    }
    #pragma unroll
    for (int o = 16; o; o >>= 1) s += __shfl_xor_sync(0xffffffffu, s, o);
    if (lane == 0) g_q[wid] = s * (1.0f / (float)HW);
}

// ---------------- 2. normalize query + split to bf16 hi/lo ----------------
__global__ void qnorm_kernel() {
    int b = blockIdx.x;
    int t = threadIdx.x;            // 128 threads, one float4 each
    float4 v = reinterpret_cast<const float4*>(g_q + (size_t)b * C_D)[t];
    float ss = v.x*v.x + v.y*v.y + v.z*v.z + v.w*v.w;
    #pragma unroll
    for (int o = 16; o; o >>= 1) ss += __shfl_xor_sync(0xffffffffu, ss, o);
    __shared__ float sred[4];
    if ((t & 31) == 0) sred[t >> 5] = ss;
    __syncthreads();
    float inv = 1.0f / sqrtf(sred[0] + sred[1] + sred[2] + sred[3]);
    float n[4] = { v.x*inv, v.y*inv, v.z*inv, v.w*inv };
    __nv_bfloat16 h[4]; float l[4];
    #pragma unroll
    for (int i = 0; i < 4; ++i) { h[i] = __float2bfloat16_rn(n[i]); l[i] = n[i] - __bfloat162float(h[i]); }
    __nv_bfloat162* qh2 = reinterpret_cast<__nv_bfloat162*>(g_qh + (size_t)b * C_D);
    __nv_bfloat162* ql2 = reinterpret_cast<__nv_bfloat162*>(g_ql + (size_t)b * C_D);
    qh2[2*t]   = __nv_bfloat162(h[0], h[1]);
    qh2[2*t+1] = __nv_bfloat162(h[2], h[3]);
    ql2[2*t]   = __floats2bfloat162_rn(l[0], l[1]);
    ql2[2*t+1] = __floats2bfloat162_rn(l[2], l[3]);
}

// ---------------- 3. normalize keys + split to bf16 hi/lo (warp per row) ----------------
__global__ void kprep_kernel(const float* __restrict__ keys) {
    int row  = (blockIdx.x * blockDim.x + threadIdx.x) >> 5;
    int lane = threadIdx.x & 31;
    const float4* p = reinterpret_cast<const float4*>(keys + (size_t)row * C_D);
    float4 v[4];
    float ss = 0.f;
    #pragma unroll
    for (int i = 0; i < 4; ++i) {
        v[i] = p[lane + 32 * i];
        ss += v[i].x*v[i].x + v[i].y*v[i].y + v[i].z*v[i].z + v[i].w*v[i].w;
    }
    #pragma unroll
    for (int o = 16; o; o >>= 1) ss += __shfl_xor_sync(0xffffffffu, ss, o);
    float inv = 1.0f / sqrtf(ss);
    __nv_bfloat162* kh2 = reinterpret_cast<__nv_bfloat162*>(g_kh + (size_t)row * C_D);
    __nv_bfloat162* kl2 = reinterpret_cast<__nv_bfloat162*>(g_kl + (size_t)row * C_D);
    #pragma unroll
    for (int i = 0; i < 4; ++i) {
        int u = lane + 32 * i;                  // float4 unit -> cols [4u, 4u+4)
        float n[4] = { v[i].x*inv, v[i].y*inv, v[i].z*inv, v[i].w*inv };
        __nv_bfloat16 h[4]; float l[4];
        #pragma unroll
        for (int j = 0; j < 4; ++j) { h[j] = __float2bfloat16_rn(n[j]); l[j] = n[j] - __bfloat162float(h[j]); }
        kh2[2*u]   = __nv_bfloat162(h[0], h[1]);
        kh2[2*u+1] = __nv_bfloat162(h[2], h[3]);
        kl2[2*u]   = __floats2bfloat162_rn(l[0], l[1]);
        kl2[2*u+1] = __floats2bfloat162_rn(l[2], l[3]);
    }
}

// ---------------- 4. sim GEMM via HMMA mma.sync bf16 (3-term hi/lo split) ----------------
// CTA tile 128(b) x 128(m). 8 warps as 4(m-rows) x 2(n-cols): warp tile 32x64.
// K chunks of 64 cols; smem 128B rows with SW128 xor swizzle; 3-stage cp.async.
// Grid is (2 batch-slabs, 512 m-tiles): the two CTAs sharing a key tile are
// ADJACENT in linear block order -> second kh/kl read hits L2 instead of DRAM.
#define GEMM_BM 128
#define GEMM_BN 128
#define KC      64
#define NCH     (C_D / KC)       // 8
#define MAT_SZ  16384u           // 128 rows x 128 B
#define STG_SZ  65536u           // qh | ql | kh | kl

extern __shared__ char g_dynsmem[];

__device__ __forceinline__ void load_stage(int ch, int tid, int mm, int bb, uint32_t stg) {
    const int koff = ch * KC;
    const __nv_bfloat16* src0 = g_qh + (size_t)bb * C_D + koff;
    const __nv_bfloat16* src1 = g_ql + (size_t)bb * C_D + koff;
    const __nv_bfloat16* src2 = g_kh + (size_t)mm * C_D + koff;
    const __nv_bfloat16* src3 = g_kl + (size_t)mm * C_D + koff;
    const __nv_bfloat16* srcs[4] = { src0, src1, src2, src3 };
    #pragma unroll
    for (int m = 0; m < 4; ++m) {
        const uint32_t mb = stg + (uint32_t)m * MAT_SZ;
        const __nv_bfloat16* s = srcs[m];
        #pragma unroll
        for (int i = 0; i < 4; ++i) {
            int u = i * 256 + tid;            // 1024 x 16B transfers
            int r = u >> 3, sl = u & 7;
            cp16(mb + (uint32_t)(r * 128) + (uint32_t)(((sl ^ (r & 7)) & 7) << 4),
                 s + (size_t)r * C_D + sl * 8);
        }
    }
    asm volatile("cp.async.commit_group;" ::: "memory");
}

__global__ void __launch_bounds__(256, 1) gemm_hmma_kernel() {
    const int tid  = threadIdx.x;
    const int wid  = tid >> 5;
    const int lane = tid & 31;
    const int mm   = blockIdx.y * GEMM_BN;   // key tile (slow axis)
    const int bb   = blockIdx.x * GEMM_BM;   // batch slab (fast axis -> adjacent CTAs share keys)
    const int wrow = (wid & 3) * 32;      // warp m-offset within tile
    const int wcol = (wid >> 2) * 64;     // warp n-offset within tile
    const uint32_t sbase = (smem_u32(g_dynsmem) + 1023u) & ~1023u;

    float acc[2][8][4];
    #pragma unroll
    for (int i = 0; i < 2; ++i)
        #pragma unroll
        for (int j = 0; j < 8; ++j)
            #pragma unroll
            for (int q = 0; q < 4; ++q) acc[i][j][q] = 0.f;

    load_stage(0, tid, mm, bb, sbase + 0u * STG_SZ);
    load_stage(1, tid, mm, bb, sbase + 1u * STG_SZ);

    const int arow = ((lane >> 3) & 1) * 8 + (lane & 7);   // A ldmatrix row-in-tile
    const int brow = (lane >> 4) * 8 + (lane & 7);         // B ldmatrix row-in-pair

    for (int ch = 0; ch < NCH; ++ch) {
        if (ch < NCH - 1) cp_wait<1>(); else cp_wait<0>();
        __syncthreads();
        if (ch + 2 < NCH) load_stage(ch + 2, tid, mm, bb, sbase + (uint32_t)((ch + 2) % 3) * STG_SZ);

        const uint32_t st   = sbase + (uint32_t)(ch % 3) * STG_SZ;
        const uint32_t s_qh = st;
        const uint32_t s_ql = st + MAT_SZ;
        const uint32_t s_kh = st + 2u * MAT_SZ;
        const uint32_t s_kl = st + 3u * MAT_SZ;

        #pragma unroll
        for (int stp = 0; stp < 4; ++stp) {               // 4 x k16 per chunk
            uint32_t ah[2][4], al[2][4], bh[8][2], bl[8][2];
            const int aslot = 2 * stp + (lane >> 4);
            const int bslot = 2 * stp + ((lane >> 3) & 1);
            #pragma unroll
            for (int i = 0; i < 2; ++i) {
                int r = wrow + i * 16 + arow;
                ldsm4(ah[i], swz(s_qh, r, aslot));
                ldsm4(al[i], swz(s_ql, r, aslot));
            }
            #pragma unroll
            for (int jp = 0; jp < 4; ++jp) {
                int r = wcol + jp * 16 + brow;
                ldsm4(&bh[2 * jp][0], swz(s_kh, r, bslot));
                ldsm4(&bl[2 * jp][0], swz(s_kl, r, bslot));
            }
            #pragma unroll
            for (int i = 0; i < 2; ++i)
                #pragma unroll
                for (int j = 0; j < 8; ++j) {
                    mma_bf16(acc[i][j], ah[i], bh[j]);   // qh . kh
                    mma_bf16(acc[i][j], al[i], bh[j]);   // ql . kh
                    mma_bf16(acc[i][j], ah[i], bl[j]);   // qh . kl
                }
        }
    }

    // epilogue: direct global stores (rows = batch, cols = keys)
    #pragma unroll
    for (int i = 0; i < 2; ++i) {
        const int r0 = bb + wrow + i * 16 + (lane >> 2);
        #pragma unroll
        for (int j = 0; j < 8; ++j) {
            const int c = mm + wcol + j * 8 + 2 * (lane & 3);
            float* p = g_sim + (size_t)r0 * M_N + c;
            *reinterpret_cast<float2*>(p)                    = make_float2(acc[i][j][0], acc[i][j][1]);
            *reinterpret_cast<float2*>(p + (size_t)8 * M_N)  = make_float2(acc[i][j][2], acc[i][j][3]);
        }
    }
}

// ---------------- 5. per-row top-32 via 13-bit radix select ----------------
__global__ void __launch_bounds__(256) topk_kernel() {
    const int b   = blockIdx.x;
    const int tid = threadIdx.x;
    const float4* row4 = reinterpret_cast<const float4*>(g_sim + (size_t)b * M_N);

    __shared__ unsigned int       s_hist[8192];   // 32 KB; reused as eq-candidate list
    __shared__ unsigned int       s_coarse[256];
    __shared__ unsigned long long s_gt[TOPK];
    __shared__ unsigned long long s_rv[256];
    __shared__ int                s_rp[256];
    __shared__ int s_T, s_cntgt, s_nGT, s_nEQ;

    #pragma unroll
    for (int i = 0; i < 32; ++i) s_hist[tid + i * 256] = 0;
    if (tid == 0) { s_nGT = 0; s_nEQ = 0; }
    __syncthreads();

    for (int i = tid; i < M_N / 4; i += 256) {
        float4 v = row4[i];
        atomicAdd(&s_hist[fkey(v.x) >> 19], 1u);
        atomicAdd(&s_hist[fkey(v.y) >> 19], 1u);
        atomicAdd(&s_hist[fkey(v.z) >> 19], 1u);
        atomicAdd(&s_hist[fkey(v.w) >> 19], 1u);
    }
    __syncthreads();

    {
        unsigned int s = 0;
        #pragma unroll
        for (int j = 0; j < 32; ++j) s += s_hist[tid * 32 + j];
        s_coarse[tid] = s;
    }
    __syncthreads();
    if (tid == 0) {
        unsigned int acc = 0;
        int cb = 0;
        for (int t = 255; t >= 0; --t) {
            if (acc + s_coarse[t] >= TOPK) { cb = t; break; }
            acc += s_coarse[t];
        }
        int T = cb * 32;
        for (int j = 31; j >= 0; --j) {
            unsigned int c = s_hist[cb * 32 + j];
            if (acc + c >= TOPK) { T = cb * 32 + j; break; }
            acc += c;
        }
        s_T = T; s_cntgt = (int)acc;
    }
    __syncthreads();
    const int T      = s_T;
    const int cnt_gt = s_cntgt;
    __syncthreads();

    unsigned long long* s_eq = reinterpret_cast<unsigned long long*>(s_hist);

    for (int i = tid; i < M_N / 4; i += 256) {
        float4 v = row4[i];
        float vv[4] = { v.x, v.y, v.z, v.w };
        #pragma unroll
        for (int c = 0; c < 4; ++c) {
            unsigned int key = fkey(vv[c]);
            int bin = (int)(key >> 19);
            if (bin > T) {
                int p = atomicAdd(&s_nGT, 1);
                s_gt[p] = ((unsigned long long)key << 32) | (unsigned int)(4 * i + c);
            } else if (bin == T) {
                int p = atomicAdd(&s_nEQ, 1);
                if (p < 4096) s_eq[p] = ((unsigned long long)key << 32) | (unsigned int)(4 * i + c);
            }
        }
    }
    __syncthreads();
    const int nEQ  = min(s_nEQ, 4096);
    const int need = TOPK - cnt_gt;

    for (int i = tid; i < cnt_gt; i += 256) {
        unsigned long long e = s_gt[i];
        g_ti[b * TOPK + i] = (int)(unsigned int)e;
        g_tv[b * TOPK + i] = unfkey((unsigned int)(e >> 32));
    }

    for (int r = 0; r < need; ++r) {
        unsigned long long best = 0; int bp = -1;
        for (int i = tid; i < nEQ; i += 256) {
            unsigned long long v = s_eq[i];
            if (v > best) { best = v; bp = i; }
        }
        s_rv[tid] = best; s_rp[tid] = bp;
        __syncthreads();
        for (int sft = 128; sft > 0; sft >>= 1) {
            if (tid < sft && s_rv[tid + sft] > s_rv[tid]) {
                s_rv[tid] = s_rv[tid + sft]; s_rp[tid] = s_rp[tid + sft];
            }
            __syncthreads();
        }
        if (tid == 0) {
            unsigned long long e = s_rv[0];
            g_ti[b * TOPK + cnt_gt + r] = (int)(unsigned int)e;
            g_tv[b * TOPK + cnt_gt + r] = unfkey((unsigned int)(e >> 32));
            s_eq[s_rp[0]] = 0ull;
        }
        __syncthreads();
    }
}

// ---------------- 6. softmax + weighted gather of values ----------------
__global__ void matched_kernel(const float* __restrict__ values) {
    const int b = blockIdx.x;
    const int c = threadIdx.x;          // 512 threads
    __shared__ float sw[TOPK];
    __shared__ int   sidx[TOPK];
    if (c < TOPK) {
        sidx[c] = g_ti[b * TOPK + c];
        float v = g_tv[b * TOPK + c];
        float mx = v;
        #pragma unroll
        for (int o = 16; o; o >>= 1) mx = fmaxf(mx, __shfl_xor_sync(0xffffffffu, mx, o));
        float e = expf(v - mx);
        float s = e;
        #pragma unroll
        for (int o = 16; o; o >>= 1) s += __shfl_xor_sync(0xffffffffu, s, o);
        sw[c] = e / s;
    }
    __syncthreads();
    float acc = 0.f;
    #pragma unroll
    for (int k = 0; k < TOPK; ++k)
        acc += sw[k] * values[(size_t)sidx[k] * C_D + c];
    g_match[b * C_D + c] = acc;
}

// ---------------- 7. broadcast matched[b,c] over 28x28 spatial ----------------
__global__ void bcast_kernel(float* __restrict__ out) {
    int wid  = (blockIdx.x * blockDim.x + threadIdx.x) >> 5;
    int lane = threadIdx.x & 31;
    float v = g_match[wid];
    float4 vv = make_float4(v, v, v, v);
    float4* o = reinterpret_cast<float4*>(out) + (size_t)wid * HW4;
    #pragma unroll
    for (int i = 0; i < 7; ++i) {
        int j = lane + i * 32;
        if (j < HW4) o[j] = vv;
    }
}

// ---------------- launch ----------------
extern "C" void kernel_launch(void* const* d_in, const int* in_sizes, int n_in,
                              void* d_out, int out_size) {
    const float* x      = (const float*)d_in[0];
    const float* keys   = (const float*)d_in[1];
    const float* values = (const float*)d_in[2];
    float* out = (float*)d_out;

    static bool attr_done = false;
    const int gemm_smem = 3 * (int)STG_SZ + 1024;   // 3 stages + align slack
    if (!attr_done) {
        cudaFuncSetAttribute(gemm_hmma_kernel,
                             cudaFuncAttributeMaxDynamicSharedMemorySize, gemm_smem);
        attr_done = true;
    }

    pool_kernel <<< (B_N * C_D) / 8, 256 >>>(x);
    qnorm_kernel<<< B_N, 128 >>>();
    kprep_kernel<<< M_N / 8, 256 >>>(keys);
    gemm_hmma_kernel<<< dim3(B_N / GEMM_BM, M_N / GEMM_BN), 256, gemm_smem >>>();
    topk_kernel <<< B_N, 256 >>>();
    matched_kernel<<< B_N, C_D >>>(values);
    bcast_kernel<<< (B_N * C_D) / 8, 256 >>>(out);
}

// round 16
// speedup vs baseline: 1.0019x; 1.0009x over previous
#include <cuda_runtime.h>
#include <cuda_bf16.h>
#include <cstdint>

#define B_N   256
#define C_D   512
#define HW    784
#define HW4   196
#define M_N   65536
#define TOPK  32

// ---------------- scratch (device globals; no allocation allowed) ----------------
__device__ float g_q[B_N * C_D];                       // pooled query (fp32)
__device__ __nv_bfloat16 g_qh[B_N * C_D];              // normalized query, bf16 hi
__device__ __nv_bfloat16 g_ql[B_N * C_D];              // normalized query, bf16 lo
__device__ __nv_bfloat16 g_kh[(size_t)M_N * C_D];      // normalized keys, bf16 hi (64 MB)
__device__ __nv_bfloat16 g_kl[(size_t)M_N * C_D];      // normalized keys, bf16 lo (64 MB)
__device__ float g_sim[(size_t)B_N * M_N];             // 64 MB similarity matrix
__device__ float g_tv[B_N * TOPK];
__device__ int   g_ti[B_N * TOPK];
__device__ float g_match[B_N * C_D];

// ---------------- small helpers ----------------
__device__ __forceinline__ unsigned int fkey(float f) {
    unsigned int u = __float_as_uint(f);
    return (u & 0x80000000u) ? ~u : (u | 0x80000000u);
}
__device__ __forceinline__ float unfkey(unsigned int u) {
    u = (u & 0x80000000u) ? (u & 0x7fffffffu) : ~u;
    return __uint_as_float(u);
}
__device__ __forceinline__ uint32_t smem_u32(const void* p) {
    uint32_t a;
    asm("{ .reg .u64 t; cvta.to.shared.u64 t, %1; cvt.u32.u64 %0, t; }" : "=r"(a) : "l"(p));
    return a;
}
__device__ __forceinline__ void cp16(uint32_t dst, const void* src) {
    asm volatile("cp.async.cg.shared.global [%0], [%1], 16;" :: "r"(dst), "l"(src));
}
template <int N>
__device__ __forceinline__ void cp_wait() {
    asm volatile("cp.async.wait_group %0;" :: "n"(N) : "memory");
}
__device__ __forceinline__ void ldsm4(uint32_t* r, uint32_t addr) {
    asm volatile("ldmatrix.sync.aligned.m8n8.x4.shared.b16 {%0,%1,%2,%3}, [%4];"
        : "=r"(r[0]), "=r"(r[1]), "=r"(r[2]), "=r"(r[3]) : "r"(addr));
}
__device__ __forceinline__ void mma_bf16(float* d, const uint32_t* a, const uint32_t* b) {
    asm volatile("mma.sync.aligned.m16n8k16.row.col.f32.bf16.bf16.f32 "
        "{%0,%1,%2,%3}, {%4,%5,%6,%7}, {%8,%9}, {%0,%1,%2,%3};"
        : "+f"(d[0]), "+f"(d[1]), "+f"(d[2]), "+f"(d[3])
        : "r"(a[0]), "r"(a[1]), "r"(a[2]), "r"(a[3]), "r"(b[0]), "r"(b[1]));
}
__device__ __forceinline__ uint32_t swz(uint32_t base, int row, int slot) {
    return base + (uint32_t)(row * 128) + (uint32_t)(((slot ^ (row & 7)) & 7) << 4);
}

// ---------------- 1. global average pool ----------------
__global__ void pool_kernel(const float* __restrict__ x) {
    int wid  = (blockIdx.x * blockDim.x + threadIdx.x) >> 5;
    int lane = threadIdx.x & 31;
    const float4* p = reinterpret_cast<const float4*>(x) + (size_t)wid * HW4;
    float s = 0.f;
    #pragma unroll
    for (int i = 0; i < 7; ++i) {
        int j = lane + i * 32;
        if (j < HW4) { float4 v = p[j]; s += (v.x + v.y) + (v.z + v.w); }
    }
    #pragma unroll
    for (int o = 16; o; o >>= 1) s += __shfl_xor_sync(0xffffffffu, s, o);
    if (lane == 0) g_q[wid] = s * (1.0f / (float)HW);
}

// ---------------- 2. normalize query + split to bf16 hi/lo ----------------
__global__ void qnorm_kernel() {
    int b = blockIdx.x;
    int t = threadIdx.x;            // 128 threads, one float4 each
    float4 v = reinterpret_cast<const float4*>(g_q + (size_t)b * C_D)[t];
    float ss = v.x*v.x + v.y*v.y + v.z*v.z + v.w*v.w;
    #pragma unroll
    for (int o = 16; o; o >>= 1) ss += __shfl_xor_sync(0xffffffffu, ss, o);
    __shared__ float sred[4];
    if ((t & 31) == 0) sred[t >> 5] = ss;
    __syncthreads();
    float inv = 1.0f / sqrtf(sred[0] + sred[1] + sred[2] + sred[3]);
    float n[4] = { v.x*inv, v.y*inv, v.z*inv, v.w*inv };
    __nv_bfloat16 h[4]; float l[4];
    #pragma unroll
    for (int i = 0; i < 4; ++i) { h[i] = __float2bfloat16_rn(n[i]); l[i] = n[i] - __bfloat162float(h[i]); }
    __nv_bfloat162* qh2 = reinterpret_cast<__nv_bfloat162*>(g_qh + (size_t)b * C_D);
    __nv_bfloat162* ql2 = reinterpret_cast<__nv_bfloat162*>(g_ql + (size_t)b * C_D);
    qh2[2*t]   = __nv_bfloat162(h[0], h[1]);
    qh2[2*t+1] = __nv_bfloat162(h[2], h[3]);
    ql2[2*t]   = __floats2bfloat162_rn(l[0], l[1]);
    ql2[2*t+1] = __floats2bfloat162_rn(l[2], l[3]);
}

// ---------------- 3. normalize keys + split to bf16 hi/lo (warp per row) ----------------
__global__ void kprep_kernel(const float* __restrict__ keys) {
    int row  = (blockIdx.x * blockDim.x + threadIdx.x) >> 5;
    int lane = threadIdx.x & 31;
    const float4* p = reinterpret_cast<const float4*>(keys + (size_t)row * C_D);
    float4 v[4];
    float ss = 0.f;
    #pragma unroll
    for (int i = 0; i < 4; ++i) {
        v[i] = p[lane + 32 * i];
        ss += v[i].x*v[i].x + v[i].y*v[i].y + v[i].z*v[i].z + v[i].w*v[i].w;
    }
    #pragma unroll
    for (int o = 16; o; o >>= 1) ss += __shfl_xor_sync(0xffffffffu, ss, o);
    float inv = 1.0f / sqrtf(ss);
    __nv_bfloat162* kh2 = reinterpret_cast<__nv_bfloat162*>(g_kh + (size_t)row * C_D);
    __nv_bfloat162* kl2 = reinterpret_cast<__nv_bfloat162*>(g_kl + (size_t)row * C_D);
    #pragma unroll
    for (int i = 0; i < 4; ++i) {
        int u = lane + 32 * i;                  // float4 unit -> cols [4u, 4u+4)
        float n[4] = { v[i].x*inv, v[i].y*inv, v[i].z*inv, v[i].w*inv };
        __nv_bfloat16 h[4]; float l[4];
        #pragma unroll
        for (int j = 0; j < 4; ++j) { h[j] = __float2bfloat16_rn(n[j]); l[j] = n[j] - __bfloat162float(h[j]); }
        kh2[2*u]   = __nv_bfloat162(h[0], h[1]);
        kh2[2*u+1] = __nv_bfloat162(h[2], h[3]);
        kl2[2*u]   = __floats2bfloat162_rn(l[0], l[1]);
        kl2[2*u+1] = __floats2bfloat162_rn(l[2], l[3]);
    }
}

// ---------------- 4. sim GEMM via HMMA mma.sync bf16 (3-term hi/lo split) ----------------
// CTA tile 128(b) x 128(m). 8 warps as 4(m-rows) x 2(n-cols): warp tile 32x64.
// K chunks of 64 cols; smem 128B rows with SW128 xor swizzle; 3-stage cp.async.
// Grid is (2 batch-slabs, 512 m-tiles): the two CTAs sharing a key tile are
// ADJACENT in linear block order -> second kh/kl read hits L2 instead of DRAM.
#define GEMM_BM 128
#define GEMM_BN 128
#define KC      64
#define NCH     (C_D / KC)       // 8
#define MAT_SZ  16384u           // 128 rows x 128 B
#define STG_SZ  65536u           // qh | ql | kh | kl

extern __shared__ char g_dynsmem[];

__device__ __forceinline__ void load_stage(int ch, int tid, int mm, int bb, uint32_t stg) {
    const int koff = ch * KC;
    const __nv_bfloat16* src0 = g_qh + (size_t)bb * C_D + koff;
    const __nv_bfloat16* src1 = g_ql + (size_t)bb * C_D + koff;
    const __nv_bfloat16* src2 = g_kh + (size_t)mm * C_D + koff;
    const __nv_bfloat16* src3 = g_kl + (size_t)mm * C_D + koff;
    const __nv_bfloat16* srcs[4] = { src0, src1, src2, src3 };
    #pragma unroll
    for (int m = 0; m < 4; ++m) {
        const uint32_t mb = stg + (uint32_t)m * MAT_SZ;
        const __nv_bfloat16* s = srcs[m];
        #pragma unroll
        for (int i = 0; i < 4; ++i) {
            int u = i * 256 + tid;            // 1024 x 16B transfers
            int r = u >> 3, sl = u & 7;
            cp16(mb + (uint32_t)(r * 128) + (uint32_t)(((sl ^ (r & 7)) & 7) << 4),
                 s + (size_t)r * C_D + sl * 8);
        }
    }
    asm volatile("cp.async.commit_group;" ::: "memory");
}

__global__ void __launch_bounds__(256, 1) gemm_hmma_kernel() {
    const int tid  = threadIdx.x;
    const int wid  = tid >> 5;
    const int lane = tid & 31;
    const int mm   = blockIdx.y * GEMM_BN;   // key tile (slow axis)
    const int bb   = blockIdx.x * GEMM_BM;   // batch slab (fast axis -> adjacent CTAs share keys)
    const int wrow = (wid & 3) * 32;      // warp m-offset within tile
    const int wcol = (wid >> 2) * 64;     // warp n-offset within tile
    const uint32_t sbase = (smem_u32(g_dynsmem) + 1023u) & ~1023u;

    float acc[2][8][4];
    #pragma unroll
    for (int i = 0; i < 2; ++i)
        #pragma unroll
        for (int j = 0; j < 8; ++j)
            #pragma unroll
            for (int q = 0; q < 4; ++q) acc[i][j][q] = 0.f;

    load_stage(0, tid, mm, bb, sbase + 0u * STG_SZ);
    load_stage(1, tid, mm, bb, sbase + 1u * STG_SZ);

    const int arow = ((lane >> 3) & 1) * 8 + (lane & 7);   // A ldmatrix row-in-tile
    const int brow = (lane >> 4) * 8 + (lane & 7);         // B ldmatrix row-in-pair

    for (int ch = 0; ch < NCH; ++ch) {
        if (ch < NCH - 1) cp_wait<1>(); else cp_wait<0>();
        __syncthreads();
        if (ch + 2 < NCH) load_stage(ch + 2, tid, mm, bb, sbase + (uint32_t)((ch + 2) % 3) * STG_SZ);

        const uint32_t st   = sbase + (uint32_t)(ch % 3) * STG_SZ;
        const uint32_t s_qh = st;
        const uint32_t s_ql = st + MAT_SZ;
        const uint32_t s_kh = st + 2u * MAT_SZ;
        const uint32_t s_kl = st + 3u * MAT_SZ;

        #pragma unroll
        for (int stp = 0; stp < 4; ++stp) {               // 4 x k16 per chunk
            uint32_t ah[2][4], al[2][4], bh[8][2], bl[8][2];
            const int aslot = 2 * stp + (lane >> 4);
            const int bslot = 2 * stp + ((lane >> 3) & 1);
            #pragma unroll
            for (int i = 0; i < 2; ++i) {
                int r = wrow + i * 16 + arow;
                ldsm4(ah[i], swz(s_qh, r, aslot));
                ldsm4(al[i], swz(s_ql, r, aslot));
            }
            #pragma unroll
            for (int jp = 0; jp < 4; ++jp) {
                int r = wcol + jp * 16 + brow;
                ldsm4(&bh[2 * jp][0], swz(s_kh, r, bslot));
                ldsm4(&bl[2 * jp][0], swz(s_kl, r, bslot));
            }
            #pragma unroll
            for (int i = 0; i < 2; ++i)
                #pragma unroll
                for (int j = 0; j < 8; ++j) {
                    mma_bf16(acc[i][j], ah[i], bh[j]);   // qh . kh
                    mma_bf16(acc[i][j], al[i], bh[j]);   // ql . kh
                    mma_bf16(acc[i][j], ah[i], bl[j]);   // qh . kl
                }
        }
    }

    // epilogue: direct global stores (rows = batch, cols = keys)
    #pragma unroll
    for (int i = 0; i < 2; ++i) {
        const int r0 = bb + wrow + i * 16 + (lane >> 2);
        #pragma unroll
        for (int j = 0; j < 8; ++j) {
            const int c = mm + wcol + j * 8 + 2 * (lane & 3);
            float* p = g_sim + (size_t)r0 * M_N + c;
            *reinterpret_cast<float2*>(p)                    = make_float2(acc[i][j][0], acc[i][j][1]);
            *reinterpret_cast<float2*>(p + (size_t)8 * M_N)  = make_float2(acc[i][j][2], acc[i][j][3]);
        }
    }
}

// ---------------- 5. per-row top-32 via 13-bit radix select ----------------
__global__ void __launch_bounds__(256) topk_kernel() {
    const int b   = blockIdx.x;
    const int tid = threadIdx.x;
    const float4* row4 = reinterpret_cast<const float4*>(g_sim + (size_t)b * M_N);

    __shared__ unsigned int       s_hist[8192];   // 32 KB; reused as eq-candidate list
    __shared__ unsigned int       s_coarse[256];
    __shared__ unsigned long long s_gt[TOPK];
    __shared__ unsigned long long s_rv[256];
    __shared__ int                s_rp[256];
    __shared__ int s_T, s_cntgt, s_nGT, s_nEQ;

    #pragma unroll
    for (int i = 0; i < 32; ++i) s_hist[tid + i * 256] = 0;
    if (tid == 0) { s_nGT = 0; s_nEQ = 0; }
    __syncthreads();

    for (int i = tid; i < M_N / 4; i += 256) {
        float4 v = row4[i];
        atomicAdd(&s_hist[fkey(v.x) >> 19], 1u);
        atomicAdd(&s_hist[fkey(v.y) >> 19], 1u);
        atomicAdd(&s_hist[fkey(v.z) >> 19], 1u);
        atomicAdd(&s_hist[fkey(v.w) >> 19], 1u);
    }
    __syncthreads();

    {
        unsigned int s = 0;
        #pragma unroll
        for (int j = 0; j < 32; ++j) s += s_hist[tid * 32 + j];
        s_coarse[tid] = s;
    }
    __syncthreads();
    if (tid == 0) {
        unsigned int acc = 0;
        int cb = 0;
        for (int t = 255; t >= 0; --t) {
            if (acc + s_coarse[t] >= TOPK) { cb = t; break; }
            acc += s_coarse[t];
        }
        int T = cb * 32;
        for (int j = 31; j >= 0; --j) {
            unsigned int c = s_hist[cb * 32 + j];
            if (acc + c >= TOPK) { T = cb * 32 + j; break; }
            acc += c;
        }
        s_T = T; s_cntgt = (int)acc;
    }
    __syncthreads();
    const int T      = s_T;
    const int cnt_gt = s_cntgt;
    __syncthreads();

    unsigned long long* s_eq = reinterpret_cast<unsigned long long*>(s_hist);

    for (int i = tid; i < M_N / 4; i += 256) {
        float4 v = row4[i];
        float vv[4] = { v.x, v.y, v.z, v.w };
        #pragma unroll
        for (int c = 0; c < 4; ++c) {
            unsigned int key = fkey(vv[c]);
            int bin = (int)(key >> 19);
            if (bin > T) {
                int p = atomicAdd(&s_nGT, 1);
                s_gt[p] = ((unsigned long long)key << 32) | (unsigned int)(4 * i + c);
            } else if (bin == T) {
                int p = atomicAdd(&s_nEQ, 1);
                if (p < 4096) s_eq[p] = ((unsigned long long)key << 32) | (unsigned int)(4 * i + c);
            }
        }
    }
    __syncthreads();
    const int nEQ  = min(s_nEQ, 4096);
    const int need = TOPK - cnt_gt;

    for (int i = tid; i < cnt_gt; i += 256) {
        unsigned long long e = s_gt[i];
        g_ti[b * TOPK + i] = (int)(unsigned int)e;
        g_tv[b * TOPK + i] = unfkey((unsigned int)(e >> 32));
    }

    for (int r = 0; r < need; ++r) {
        unsigned long long best = 0; int bp = -1;
        for (int i = tid; i < nEQ; i += 256) {
            unsigned long long v = s_eq[i];
            if (v > best) { best = v; bp = i; }
        }
        s_rv[tid] = best; s_rp[tid] = bp;
        __syncthreads();
        for (int sft = 128; sft > 0; sft >>= 1) {
            if (tid < sft && s_rv[tid + sft] > s_rv[tid]) {
                s_rv[tid] = s_rv[tid + sft]; s_rp[tid] = s_rp[tid + sft];
            }
            __syncthreads();
        }
        if (tid == 0) {
            unsigned long long e = s_rv[0];
            g_ti[b * TOPK + cnt_gt + r] = (int)(unsigned int)e;
            g_tv[b * TOPK + cnt_gt + r] = unfkey((unsigned int)(e >> 32));
            s_eq[s_rp[0]] = 0ull;
        }
        __syncthreads();
    }
}

// ---------------- 6. softmax + weighted gather of values ----------------
__global__ void matched_kernel(const float* __restrict__ values) {
    const int b = blockIdx.x;
    const int c = threadIdx.x;          // 512 threads
    __shared__ float sw[TOPK];
    __shared__ int   sidx[TOPK];
    if (c < TOPK) {
        sidx[c] = g_ti[b * TOPK + c];
        float v = g_tv[b * TOPK + c];
        float mx = v;
        #pragma unroll
        for (int o = 16; o; o >>= 1) mx = fmaxf(mx, __shfl_xor_sync(0xffffffffu, mx, o));
        float e = expf(v - mx);
        float s = e;
        #pragma unroll
        for (int o = 16; o; o >>= 1) s += __shfl_xor_sync(0xffffffffu, s, o);
        sw[c] = e / s;
    }
    __syncthreads();
    float acc = 0.f;
    #pragma unroll
    for (int k = 0; k < TOPK; ++k)
        acc += sw[k] * values[(size_t)sidx[k] * C_D + c];
    g_match[b * C_D + c] = acc;
}

// ---------------- 7. broadcast matched[b,c] over 28x28 spatial ----------------
__global__ void bcast_kernel(float* __restrict__ out) {
    int wid  = (blockIdx.x * blockDim.x + threadIdx.x) >> 5;
    int lane = threadIdx.x & 31;
    float v = g_match[wid];
    float4 vv = make_float4(v, v, v, v);
    float4* o = reinterpret_cast<float4*>(out) + (size_t)wid * HW4;
    #pragma unroll
    for (int i = 0; i < 7; ++i) {
        int j = lane + i * 32;
        if (j < HW4) o[j] = vv;
    }
}

// ---------------- launch ----------------
extern "C" void kernel_launch(void* const* d_in, const int* in_sizes, int n_in,
                              void* d_out, int out_size) {
    const float* x      = (const float*)d_in[0];
    const float* keys   = (const float*)d_in[1];
    const float* values = (const float*)d_in[2];
    float* out = (float*)d_out;

    static bool attr_done = false;
    const int gemm_smem = 3 * (int)STG_SZ + 1024;   // 3 stages + align slack
    if (!attr_done) {
        cudaFuncSetAttribute(gemm_hmma_kernel,
                             cudaFuncAttributeMaxDynamicSharedMemorySize, gemm_smem);
        attr_done = true;
    }

    pool_kernel <<< (B_N * C_D) / 8, 256 >>>(x);
    qnorm_kernel<<< B_N, 128 >>>();
    kprep_kernel<<< M_N / 8, 256 >>>(keys);
    gemm_hmma_kernel<<< dim3(B_N / GEMM_BM, M_N / GEMM_BN), 256, gemm_smem >>>();
    topk_kernel <<< B_N, 256 >>>();
    matched_kernel<<< B_N, C_D >>>(values);
    bcast_kernel<<< (B_N * C_D) / 8, 256 >>>(out);
}